// round 1
// baseline (speedup 1.0000x reference)
#include <cuda_runtime.h>
#include <math.h>

#define N_TOK 4096
#define D_DIM 2048
#define N_EXP 8
#define TOPK  2
#define CAP   512

// Scratch (static device globals — no allocation)
__device__ int g_choice[N_TOK * TOPK];
__device__ int g_slot[N_TOK * TOPK];

// ---------------------------------------------------------------------------
// Kernel 1: logits = x @ W, top-2, softmax. One warp per token.
// Writes gate_weights + expert_indices (as float) into d_out tail regions,
// and expert choices into g_choice.
// ---------------------------------------------------------------------------
__global__ void k_logits_topk(const float* __restrict__ x,
                              const float* __restrict__ W,
                              float* __restrict__ out) {
    int gw   = (blockIdx.x * blockDim.x + threadIdx.x) >> 5;  // token id
    int lane = threadIdx.x & 31;
    if (gw >= N_TOK) return;

    const float4* xr = reinterpret_cast<const float4*>(x) + (size_t)gw * (D_DIM / 4);
    const float4* w4 = reinterpret_cast<const float4*>(W);

    float acc[8] = {0.f, 0.f, 0.f, 0.f, 0.f, 0.f, 0.f, 0.f};

    #pragma unroll
    for (int i = 0; i < (D_DIM / 4) / 32; i++) {   // 16 iters
        int j = i * 32 + lane;                      // float4 index into row
        float4 xv = __ldg(&xr[j]);
        int d = j * 4;
        float xs[4] = {xv.x, xv.y, xv.z, xv.w};
        #pragma unroll
        for (int r = 0; r < 4; r++) {
            float4 w0 = __ldg(&w4[(d + r) * 2 + 0]);   // W[d+r][0..3]
            float4 w1 = __ldg(&w4[(d + r) * 2 + 1]);   // W[d+r][4..7]
            acc[0] += xs[r] * w0.x; acc[1] += xs[r] * w0.y;
            acc[2] += xs[r] * w0.z; acc[3] += xs[r] * w0.w;
            acc[4] += xs[r] * w1.x; acc[5] += xs[r] * w1.y;
            acc[6] += xs[r] * w1.z; acc[7] += xs[r] * w1.w;
        }
    }

    // Warp reduce all 8 logits (xor so every lane ends with full sums)
    #pragma unroll
    for (int e = 0; e < 8; e++) {
        #pragma unroll
        for (int off = 16; off > 0; off >>= 1)
            acc[e] += __shfl_xor_sync(0xffffffffu, acc[e], off);
    }

    if (lane == 0) {
        // Top-2 (strict > keeps lowest index on ties, matching lax.top_k)
        float best = -INFINITY, sec = -INFINITY;
        int bi = 0, si = 0;
        #pragma unroll
        for (int e = 0; e < 8; e++) {
            float v = acc[e];
            if (v > best)     { sec = best; si = bi; best = v; bi = e; }
            else if (v > sec) { sec = v;    si = e; }
        }
        // softmax over [best, sec]
        float g0 = 1.0f / (1.0f + expf(sec - best));

        float* gate = out + (size_t)N_TOK * N_EXP * CAP;
        float* idxf = gate + N_TOK * TOPK;
        gate[gw * 2 + 0] = g0;
        gate[gw * 2 + 1] = 1.0f - g0;
        idxf[gw * 2 + 0] = (float)bi;
        idxf[gw * 2 + 1] = (float)si;
        g_choice[gw * 2 + 0] = bi;
        g_choice[gw * 2 + 1] = si;
    }
}

// ---------------------------------------------------------------------------
// Kernel 2: per-(k,expert) running-count prefix scan over 4096 tokens.
// 16 blocks (one per (k,e)), 1024 threads, 4 tokens/thread.
// Writes capacity slot (or -1 if over capacity) into g_slot.
// ---------------------------------------------------------------------------
__global__ void k_scan() {
    int k = blockIdx.x >> 3;
    int e = blockIdx.x & 7;
    int tid  = threadIdx.x;
    int lane = tid & 31;
    int wid  = tid >> 5;

    __shared__ int warp_sums[32];

    int n0 = tid * 4;
    int flags[4];
    int localex[4];
    int s = 0;
    #pragma unroll
    for (int j = 0; j < 4; j++) {
        flags[j]   = (g_choice[(n0 + j) * 2 + k] == e) ? 1 : 0;
        localex[j] = s;
        s += flags[j];
    }

    // inclusive warp scan of per-thread sums
    int inc = s;
    #pragma unroll
    for (int off = 1; off < 32; off <<= 1) {
        int v = __shfl_up_sync(0xffffffffu, inc, off);
        if (lane >= off) inc += v;
    }
    if (lane == 31) warp_sums[wid] = inc;
    __syncthreads();

    if (wid == 0) {
        int v = warp_sums[lane];
        int winc = v;
        #pragma unroll
        for (int off = 1; off < 32; off <<= 1) {
            int u = __shfl_up_sync(0xffffffffu, winc, off);
            if (lane >= off) winc += u;
        }
        warp_sums[lane] = winc - v;  // exclusive warp offsets
    }
    __syncthreads();

    int thread_prefix = warp_sums[wid] + (inc - s);  // exclusive prefix for this thread

    #pragma unroll
    for (int j = 0; j < 4; j++) {
        if (flags[j]) {
            int pri = thread_prefix + localex[j] + 1;  // inclusive 1-based priority
            g_slot[(n0 + j) * 2 + k] = (pri <= CAP) ? (pri - 1) : -1;
        }
    }
}

// ---------------------------------------------------------------------------
// Kernel 3: zero the dispatcher region (16.78M floats = 4.19M float4).
// ---------------------------------------------------------------------------
__global__ void k_zero(float4* __restrict__ out) {
    size_t i = (size_t)blockIdx.x * blockDim.x + threadIdx.x;
    out[i] = make_float4(0.f, 0.f, 0.f, 0.f);
}

// ---------------------------------------------------------------------------
// Kernel 4: scatter the ones.
// ---------------------------------------------------------------------------
__global__ void k_scatter(float* __restrict__ out) {
    int i = blockIdx.x * blockDim.x + threadIdx.x;  // 0..8191
    int slot = g_slot[i];
    if (slot >= 0) {
        int n = i >> 1;
        int e = g_choice[i];
        out[(size_t)n * (N_EXP * CAP) + e * CAP + slot] = 1.0f;
    }
}

// ---------------------------------------------------------------------------
extern "C" void kernel_launch(void* const* d_in, const int* in_sizes, int n_in,
                              void* d_out, int out_size) {
    const float* x = (const float*)d_in[0];   // [4096, 2048]
    const float* W = (const float*)d_in[1];   // [2048, 8]
    float* out = (float*)d_out;

    k_logits_topk<<<N_TOK / 8, 256>>>(x, W, out);            // 4096 warps
    k_scan<<<16, 1024>>>();
    k_zero<<<(N_TOK * N_EXP * CAP / 4) / 256, 256>>>((float4*)out);
    k_scatter<<<(N_TOK * TOPK) / 256, 256>>>(out);
}

// round 2
// speedup vs baseline: 2.9434x; 2.9434x over previous
#include <cuda_runtime.h>
#include <math.h>

#define N_TOK 4096
#define D_DIM 2048
#define N_EXP 8
#define TOPK  2
#define CAP   512
#define WT_PITCH 1028   // floats per smem W row (pad avoids transpose-store conflicts)

// Scratch (static device globals — no allocation)
__device__ int g_choice[N_TOK * TOPK];
__device__ int g_slot[N_TOK * TOPK];

// ---------------------------------------------------------------------------
// Kernel 1: logits = x @ W, top-2, softmax. 2 tokens per warp.
// W staged in smem TRANSPOSED (wt[e][d]) so lane loads are consecutive
// float4s -> conflict-free LDS, one LDS.128 feeds 8 FFMAs (2 tokens x 4).
// ---------------------------------------------------------------------------
__global__ __launch_bounds__(256) void k_logits_topk(
        const float* __restrict__ x,
        const float* __restrict__ W,
        float* __restrict__ out) {
    __shared__ float wt[N_EXP * WT_PITCH];   // 8 x 1028 floats = 32.9 KB

    int tid  = threadIdx.x;
    int lane = tid & 31;
    int wrp  = tid >> 5;
    int gw   = blockIdx.x * 8 + wrp;     // global warp id, 0..2047
    int t0   = gw * 2;                   // first of 2 tokens

    const float4* x4 = reinterpret_cast<const float4*>(x);

    float acc0[8] = {0,0,0,0,0,0,0,0};
    float acc1[8] = {0,0,0,0,0,0,0,0};

    #pragma unroll
    for (int p = 0; p < 2; p++) {        // two 1024-d phases
        // cooperative transpose-load of W[p*1024 .. +1024)[e] -> wt[e][d]
        #pragma unroll
        for (int idx = tid; idx < 1024 * N_EXP; idx += 256) {
            int dl = idx >> 3;
            int e  = idx & 7;
            wt[e * WT_PITCH + dl] = W[(p * 1024 + dl) * N_EXP + e];
        }
        __syncthreads();

        #pragma unroll
        for (int i = 0; i < 8; i++) {
            int j = i * 32 + lane;       // float4 index within 1024-d phase
            float4 xv0 = __ldg(&x4[(size_t)t0       * (D_DIM/4) + p * 256 + j]);
            float4 xv1 = __ldg(&x4[(size_t)(t0 + 1) * (D_DIM/4) + p * 256 + j]);
            #pragma unroll
            for (int e = 0; e < N_EXP; e++) {
                float4 w = *reinterpret_cast<const float4*>(&wt[e * WT_PITCH + j * 4]);
                acc0[e] += xv0.x * w.x + xv0.y * w.y + xv0.z * w.z + xv0.w * w.w;
                acc1[e] += xv1.x * w.x + xv1.y * w.y + xv1.z * w.z + xv1.w * w.w;
            }
        }
        __syncthreads();
    }

    // warp-reduce all 16 logits
    #pragma unroll
    for (int e = 0; e < N_EXP; e++) {
        #pragma unroll
        for (int off = 16; off > 0; off >>= 1) {
            acc0[e] += __shfl_xor_sync(0xffffffffu, acc0[e], off);
            acc1[e] += __shfl_xor_sync(0xffffffffu, acc1[e], off);
        }
    }

    if (lane == 0) {
        float* gate = out + (size_t)N_TOK * N_EXP * CAP;
        float* idxf = gate + N_TOK * TOPK;
        #pragma unroll
        for (int t = 0; t < 2; t++) {
            float* a = t ? acc1 : acc0;
            int tok = t0 + t;
            float best = -INFINITY, sec = -INFINITY;
            int bi = 0, si = 0;
            #pragma unroll
            for (int e = 0; e < N_EXP; e++) {
                float v = a[e];
                if (v > best)     { sec = best; si = bi; best = v; bi = e; }
                else if (v > sec) { sec = v;    si = e; }
            }
            float g0 = 1.0f / (1.0f + expf(sec - best));
            gate[tok * 2 + 0] = g0;
            gate[tok * 2 + 1] = 1.0f - g0;
            idxf[tok * 2 + 0] = (float)bi;
            idxf[tok * 2 + 1] = (float)si;
            g_choice[tok * 2 + 0] = bi;
            g_choice[tok * 2 + 1] = si;
        }
    }
}

// ---------------------------------------------------------------------------
// Kernel 2: per-(k,expert) running-count prefix scan over 4096 tokens.
// 16 blocks (one per (k,e)), 1024 threads, 4 tokens/thread.
// ---------------------------------------------------------------------------
__global__ void k_scan() {
    int k = blockIdx.x >> 3;
    int e = blockIdx.x & 7;
    int tid  = threadIdx.x;
    int lane = tid & 31;
    int wid  = tid >> 5;

    __shared__ int warp_sums[32];

    int n0 = tid * 4;
    int flags[4];
    int localex[4];
    int s = 0;
    #pragma unroll
    for (int j = 0; j < 4; j++) {
        flags[j]   = (g_choice[(n0 + j) * 2 + k] == e) ? 1 : 0;
        localex[j] = s;
        s += flags[j];
    }

    int inc = s;
    #pragma unroll
    for (int off = 1; off < 32; off <<= 1) {
        int v = __shfl_up_sync(0xffffffffu, inc, off);
        if (lane >= off) inc += v;
    }
    if (lane == 31) warp_sums[wid] = inc;
    __syncthreads();

    if (wid == 0) {
        int v = warp_sums[lane];
        int winc = v;
        #pragma unroll
        for (int off = 1; off < 32; off <<= 1) {
            int u = __shfl_up_sync(0xffffffffu, winc, off);
            if (lane >= off) winc += u;
        }
        warp_sums[lane] = winc - v;
    }
    __syncthreads();

    int thread_prefix = warp_sums[wid] + (inc - s);

    #pragma unroll
    for (int j = 0; j < 4; j++) {
        if (flags[j]) {
            int pri = thread_prefix + localex[j] + 1;
            g_slot[(n0 + j) * 2 + k] = (pri <= CAP) ? (pri - 1) : -1;
        }
    }
}

// ---------------------------------------------------------------------------
// Kernel 3 (fused zero+scatter): one block per token row (8*512 floats).
// Pure coalesced STG.128; values computed from the token's 2 (expert,slot).
// ---------------------------------------------------------------------------
__global__ __launch_bounds__(256) void k_fill(float4* __restrict__ out) {
    int n   = blockIdx.x;
    int tid = threadIdx.x;

    int c0 = g_choice[n * 2 + 0];
    int c1 = g_choice[n * 2 + 1];
    int s0 = g_slot[n * 2 + 0];
    int s1 = g_slot[n * 2 + 1];
    int o0 = (s0 >= 0) ? c0 * CAP + s0 : -1;   // float index within row
    int o1 = (s1 >= 0) ? c1 * CAP + s1 : -1;

    float4* row = out + (size_t)n * (N_EXP * CAP / 4);

    #pragma unroll
    for (int k = 0; k < 4; k++) {
        int g = k * 256 + tid;         // float4 index within row [0,1024)
        int f = g * 4;                 // first float index
        float4 v;
        v.x = (o0 == f     || o1 == f    ) ? 1.0f : 0.0f;
        v.y = (o0 == f + 1 || o1 == f + 1) ? 1.0f : 0.0f;
        v.z = (o0 == f + 2 || o1 == f + 2) ? 1.0f : 0.0f;
        v.w = (o0 == f + 3 || o1 == f + 3) ? 1.0f : 0.0f;
        row[g] = v;
    }
}

// ---------------------------------------------------------------------------
extern "C" void kernel_launch(void* const* d_in, const int* in_sizes, int n_in,
                              void* d_out, int out_size) {
    const float* x = (const float*)d_in[0];   // [4096, 2048]
    const float* W = (const float*)d_in[1];   // [2048, 8]
    float* out = (float*)d_out;

    k_logits_topk<<<256, 256>>>(x, W, out);
    k_scan<<<16, 1024>>>();
    k_fill<<<N_TOK, 256>>>((float4*)out);
}